// round 13
// baseline (speedup 1.0000x reference)
#include <cuda_runtime.h>
#include <cuda_fp16.h>
#include <math.h>
#include <stdint.h>

// Problem constants
#define Bv   2
#define Sv   2048
#define Hv   1024
#define NHv  16
#define HDv  64
#define H3   (3 * Hv)
#define MSEQ (Bv * Sv)          // 4096 rows

// softmax scale folded into Q and mask: (1/8) * log2(e)
#define QSCALE 0.18033688011112042f

// Scratch (device globals: allocation-guard safe; zero-initialized at load,
// and re-zeroed by the last proj CTA each launch -> replay-safe)
__device__ __half g_x [(size_t)MSEQ * Hv];
__device__ __half g_wq[(size_t)H3 * Hv];
__device__ __half g_wo[(size_t)Hv * Hv];
__device__ __half g_qkv[(size_t)MSEQ * H3];
__device__ __half g_av[(size_t)MSEQ * Hv];
__device__ float  g_mask[Sv];            // mask * QSCALE
__device__ int    g_cvtx[32];            // x row-block conversion (8 subs each)
__device__ int    g_cvtw[24];            // wq row-block conversion
__device__ int    g_cvtwo[8];            // wo row-block conversion
__device__ int    g_cvtm;                // mask conversion
__device__ int    g_qkvf[768];           // per qkv 128x128 tile completion
__device__ int    g_flags[32];           // per 128-row-block attention completion
__device__ int    g_done;                // proj CTA completion counter

// ============================================================================
// Helpers
// ============================================================================
__device__ __forceinline__ uint32_t smem_to_u32(const void* smem_ptr) {
    uint32_t addr;
    asm("{ .reg .u64 tmp; cvta.to.shared.u64 tmp, %1; cvt.u32.u64 %0, tmp; }"
        : "=r"(addr) : "l"(smem_ptr));
    return addr;
}

__device__ __forceinline__ void ldsm_x4(uint32_t addr, uint32_t r[4]) {
    asm volatile("ldmatrix.sync.aligned.m8n8.x4.shared.b16 {%0,%1,%2,%3}, [%4];"
        : "=r"(r[0]), "=r"(r[1]), "=r"(r[2]), "=r"(r[3]) : "r"(addr));
}

__device__ __forceinline__ void ldsm_x4_t(uint32_t addr, uint32_t r[4]) {
    asm volatile("ldmatrix.sync.aligned.m8n8.x4.trans.shared.b16 {%0,%1,%2,%3}, [%4];"
        : "=r"(r[0]), "=r"(r[1]), "=r"(r[2]), "=r"(r[3]) : "r"(addr));
}

__device__ __forceinline__ void mma_f16(float d[4], const uint32_t a[4],
                                        uint32_t b0, uint32_t b1) {
    asm volatile(
        "mma.sync.aligned.m16n8k16.row.col.f32.f16.f16.f32 "
        "{%0,%1,%2,%3}, {%4,%5,%6,%7}, {%8,%9}, {%0,%1,%2,%3};"
        : "+f"(d[0]), "+f"(d[1]), "+f"(d[2]), "+f"(d[3])
        : "r"(a[0]), "r"(a[1]), "r"(a[2]), "r"(a[3]), "r"(b0), "r"(b1));
}

__device__ __forceinline__ uint32_t pack_h2(float x, float y) {
    __half2 h = __float22half2_rn(make_float2(x, y));
    return *(uint32_t*)&h;
}

#define CP_ASYNC16(dst_u32, src_ptr) \
    asm volatile("cp.async.cg.shared.global [%0], [%1], 16;" \
        :: "r"(dst_u32), "l"(src_ptr))
#define CP_ASYNC_COMMIT() asm volatile("cp.async.commit_group;" ::: "memory")
#define CP_ASYNC_WAIT(N)  asm volatile("cp.async.wait_group %0;" :: "n"(N) : "memory")

// ============================================================================
// fp16 GEMM (NT) device body: CTA 128x128, KC=64, 3-stage cp.async pipeline.
// ============================================================================
#define SRB   144
#define MATB  (128 * SRB)
#define STGB  (2 * MATB)
#define GSM_TOTAL (3 * STGB)     // 110592 B

template<int OUT_HALF>
__device__ __forceinline__
void gemm_body(char* smem, const __half* __restrict__ A, const __half* __restrict__ W,
               const float* __restrict__ bias, float* __restrict__ C,
               __half* __restrict__ Ch, int M, int N, int K, int m0, int n0)
{
    const uint32_t smb = smem_to_u32(smem);
    const int tid = threadIdx.x;
    const int lid = tid & 31;
    const int wid = tid >> 5;
    const int wm  = wid & 3;
    const int wn  = wid >> 2;

    const uint32_t aoff = (uint32_t)((wm * 32 + (lid & 7) + ((lid >> 3) & 1) * 8) * SRB
                                     + (lid >> 4) * 16);
    const uint32_t boff = (uint32_t)((wn * 64 + (lid & 7) + (lid >> 4) * 8) * SRB
                                     + ((lid >> 3) & 1) * 16);

    float acc[2][8][4];
#pragma unroll
    for (int i = 0; i < 2; i++)
#pragma unroll
        for (int j = 0; j < 8; j++)
#pragma unroll
            for (int e = 0; e < 4; e++) acc[i][j][e] = 0.f;

    auto LOAD = [&](int buf, int chunk) {
        const uint32_t base = smb + buf * STGB;
        const int k0 = chunk * 64;
#pragma unroll
        for (int i = 0; i < 8; i++) {
            int idx = tid + i * 256;
            int mat = idx >> 10;
            int rem = idx & 1023;
            int r = rem >> 3;
            int c = rem & 7;
            const __half* src = mat
                ? W + (size_t)(n0 + r) * K + k0 + c * 8
                : A + (size_t)(m0 + r) * K + k0 + c * 8;
            CP_ASYNC16(base + (uint32_t)(mat * MATB + r * SRB + c * 16), src);
        }
        CP_ASYNC_COMMIT();
    };

    auto MMA = [&](int buf) {
        const uint32_t base = smb + buf * STGB;
#pragma unroll
        for (int kt = 0; kt < 4; kt++) {
            uint32_t a0[4], a1[4];
            ldsm_x4(base + aoff + kt * 32, a0);
            ldsm_x4(base + aoff + 16 * SRB + kt * 32, a1);
#pragma unroll
            for (int gn = 0; gn < 4; gn++) {
                uint32_t bb[4];
                ldsm_x4(base + MATB + boff + gn * (16 * SRB) + kt * 32, bb);
                mma_f16(acc[0][2 * gn],     a0, bb[0], bb[1]);
                mma_f16(acc[0][2 * gn + 1], a0, bb[2], bb[3]);
                mma_f16(acc[1][2 * gn],     a1, bb[0], bb[1]);
                mma_f16(acc[1][2 * gn + 1], a1, bb[2], bb[3]);
            }
        }
    };

    const int NCHUNK = K / 64;
    LOAD(0, 0);
    LOAD(1, 1);

    for (int i = 0; i < NCHUNK; i++) {
        if (i + 1 < NCHUNK) { CP_ASYNC_WAIT(1); } else { CP_ASYNC_WAIT(0); }
        __syncthreads();
        if (i + 2 < NCHUNK) LOAD((i + 2) % 3, i + 2);
        MMA(i % 3);
    }

#pragma unroll
    for (int mt = 0; mt < 2; mt++) {
        const int row = m0 + wm * 32 + mt * 16 + (lid >> 2);
#pragma unroll
        for (int nt = 0; nt < 8; nt++) {
            const int col = n0 + wn * 64 + nt * 8 + (lid & 3) * 2;
            const float b0 = bias[col], b1 = bias[col + 1];
            float v00 = acc[mt][nt][0] + b0, v01 = acc[mt][nt][1] + b1;
            float v10 = acc[mt][nt][2] + b0, v11 = acc[mt][nt][3] + b1;
            if (OUT_HALF) {
                const float sc = (col < Hv) ? QSCALE : 1.0f;
                v00 *= sc; v01 *= sc; v10 *= sc; v11 *= sc;
                *(uint32_t*)(Ch + (size_t)row * N + col)       = pack_h2(v00, v01);
                *(uint32_t*)(Ch + (size_t)(row + 8) * N + col) = pack_h2(v10, v11);
            } else {
                *(float2*)(C + (size_t)row * N + col)       = make_float2(v00, v01);
                *(float2*)(C + (size_t)(row + 8) * N + col) = make_float2(v10, v11);
            }
        }
    }
}

// ============================================================================
// MEGA kernel (single launch):
//   bids    0..511  : fp32->fp16 conversion sub-blocks (+ mask at bid 448)
//   bids  512..1279 : qkv GEMM tiles      (wait on cvt flags)
//   bids 1280..1791 : attention           (wait on mask + qkv tile flags)
//   bids 1792..2047 : output projection   (wait on wo cvt + attention flags)
// Last proj CTA resets ALL flags -> graph-replay-safe.
// ============================================================================
#define SRA   144
#define QTB   (128 * SRA)
#define KVTB  (64 * SRA)
#define AS_Q  0
#define AS_KV QTB
#define AS_MS (AS_KV + 3 * 2 * KVTB)

__global__ __launch_bounds__(256, 2)
void mega(const float* __restrict__ xf, const float* __restrict__ wqf,
          const float* __restrict__ wof, const float* __restrict__ maskf,
          const float* __restrict__ b_qkv, const float* __restrict__ b_o,
          float* __restrict__ out)
{
    extern __shared__ char smem[];
    const int tid = threadIdx.x;
    const int bid = blockIdx.x;

    __half* x   = g_x;
    __half* wq  = g_wq;
    __half* wo  = g_wo;
    __half* qkv = g_qkv;
    __half* av  = g_av;

    if (bid < 512) {
        // ------------------------- conversion sub-block -------------------------
        const float* src;
        __half* dst;
        int* flag;
        int rb, sub;
        if (bid < 256)       { rb = bid >> 3;          sub = bid & 7; src = xf;  dst = x;  flag = &g_cvtx[rb]; }
        else if (bid < 448)  { rb = (bid - 256) >> 3;  sub = bid & 7; src = wqf; dst = wq; flag = &g_cvtw[rb]; }
        else                 { rb = (bid - 448) >> 3;  sub = bid & 7; src = wof; dst = wo; flag = &g_cvtwo[rb]; }
        const int base4 = rb * 32768 + sub * 4096;   // float4 index (16 rows x 1024)
#pragma unroll
        for (int l = 0; l < 16; l++) {
            int j = base4 + tid + l * 256;
            float4 v = ((const float4*)src)[j];
            uint2 o;
            o.x = pack_h2(v.x, v.y);
            o.y = pack_h2(v.z, v.w);
            ((uint2*)dst)[j] = o;
        }
        if (bid == 448 && tid < 128) {               // mask: 512 floats
            float4 v = ((const float4*)maskf)[tid];
            v.x *= QSCALE; v.y *= QSCALE; v.z *= QSCALE; v.w *= QSCALE;
            ((float4*)g_mask)[tid] = v;
        }
        __threadfence();
        __syncthreads();
        if (tid == 0) {
            atomicAdd(flag, 1);
            if (bid == 448) atomicExch(&g_cvtm, 1);
        }
        return;
    }

    if (bid < 1280) {
        // ----------------------- QKV projection tile -----------------------
        const int idx = bid - 512;
        const int mb = idx / 24, nb = idx % 24;
        if (tid == 0) {
            while (atomicAdd(&g_cvtx[mb], 0) < 8) __nanosleep(100);
            while (atomicAdd(&g_cvtw[nb], 0) < 8) __nanosleep(100);
        }
        __syncthreads();
        gemm_body<1>(smem, x, wq, b_qkv, nullptr, qkv, MSEQ, H3, Hv,
                     mb * 128, nb * 128);
        __threadfence();
        __syncthreads();
        if (tid == 0) atomicExch(&g_qkvf[idx], 1);
        return;
    }

    if (bid >= 1792) {
        // ----------------------- output projection tile --------------------
        const int idx = bid - 1792;
        const int mb  = idx >> 3;
        const int nb  = idx & 7;
        if (tid == 0) {
            while (atomicAdd(&g_cvtwo[nb], 0) < 8) __nanosleep(200);
            while (atomicAdd(&g_flags[mb], 0) < NHv) __nanosleep(200);
        }
        __syncthreads();
        gemm_body<0>(smem, av, wo, b_o, out, nullptr, MSEQ, Hv, Hv,
                     mb * 128, nb * 128);

        // last proj CTA resets all flags for the next graph replay
        __shared__ int s_last;
        __syncthreads();
        if (tid == 0) s_last = (atomicAdd(&g_done, 1) == 255);
        __syncthreads();
        if (s_last) {
            for (int i = tid; i < 768; i += 256) g_qkvf[i] = 0;
            if (tid < 32) g_cvtx[tid] = 0;
            if (tid < 24) g_cvtw[tid] = 0;
            if (tid < 8)  g_cvtwo[tid] = 0;
            if (tid < 32) g_flags[tid] = 0;
            if (tid == 0) { g_cvtm = 0; g_done = 0; }
            __threadfence();
        }
        return;
    }

    // --------------------------- attention path ---------------------------
    const uint32_t smb = smem_to_u32(smem);
    const int abid = bid - 1280;
    const int lid = tid & 31;
    const int wq_ = tid >> 5;
    const int qblk = abid & 15;
    const int q0  = qblk * 128;
    const int h   = (abid >> 4) & 15;
    const int b   = abid >> 8;
    const size_t rowbase = (size_t)b * Sv;
    const int hd0 = h * HDv;

    // qkv tile flag indices this CTA depends on
    const int nbh = h >> 1;
    const int fq  = (b * 16 + qblk) * 24 + nbh;             // Q tile
    __shared__ int s_ready;   // 1 = all deps satisfied at CTA start
    if (tid == 0) s_ready = 1;
    __syncthreads();
    if (tid < 33) {
        int f;
        if (tid == 32)      f = fq;
        else if (tid < 16)  f = (b * 16 + tid) * 24 + 8 + nbh;
        else                f = (b * 16 + (tid - 16)) * 24 + 16 + nbh;
        if (atomicAdd(&g_qkvf[f], 0) == 0) atomicExch(&s_ready, 0);
    }
    __syncthreads();
    if (tid == 0) {
        while (atomicAdd(&g_cvtm, 0) == 0) __nanosleep(100);
        if (!s_ready) {
            while (atomicAdd(&g_qkvf[fq], 0) == 0) __nanosleep(100);
            while (atomicAdd(&g_qkvf[b * 384 + 8 + nbh], 0) == 0) __nanosleep(100);
            while (atomicAdd(&g_qkvf[b * 384 + 16 + nbh], 0) == 0) __nanosleep(100);
        }
    }
    __syncthreads();

    auto LOADKV = [&](int buf, int tile) {
        const int kb = tile * 64;
        const uint32_t kvb = smb + AS_KV + buf * (2 * KVTB);
#pragma unroll
        for (int i = 0; i < 4; i++) {
            int idx = tid + i * 256;
            int mat = idx >> 9;
            int rem = idx & 511;
            int r = rem >> 3, c = rem & 7;
            int off = mat ? 2 * Hv : Hv;
            CP_ASYNC16(kvb + mat * KVTB + r * SRA + c * 16,
                       qkv + (rowbase + kb + r) * H3 + off + hd0 + c * 8);
        }
        CP_ASYNC_COMMIT();
    };

    // group 0: mask + Q + KV tile 0; group 1: KV tile 1
#pragma unroll
    for (int i = 0; i < 2; i++) {
        int idx = tid + i * 256;
        CP_ASYNC16(smb + AS_MS + idx * 16, g_mask + idx * 4);
    }
#pragma unroll
    for (int i = 0; i < 4; i++) {
        int idx = tid + i * 256;
        int r = idx >> 3, c = idx & 7;
        CP_ASYNC16(smb + AS_Q + r * SRA + c * 16,
                   qkv + (rowbase + q0 + r) * H3 + hd0 + c * 8);
    }
    {
        const uint32_t kvb = smb + AS_KV;
#pragma unroll
        for (int i = 0; i < 4; i++) {
            int idx = tid + i * 256;
            int mat = idx >> 9;
            int rem = idx & 511;
            int r = rem >> 3, c = rem & 7;
            int off = mat ? 2 * Hv : Hv;
            CP_ASYNC16(kvb + mat * KVTB + r * SRA + c * 16,
                       qkv + (rowbase + r) * H3 + off + hd0 + c * 8);
        }
        CP_ASYNC_COMMIT();
    }
    LOADKV(1, 1);

    const uint32_t aoffQ = (uint32_t)((wq_ * 16 + (lid & 7) + ((lid >> 3) & 1) * 8) * SRA
                                      + (lid >> 4) * 16);
    const uint32_t boffK = (uint32_t)(((lid & 7) + (lid >> 4) * 8) * SRA
                                      + ((lid >> 3) & 1) * 16);
    const uint32_t voffV = (uint32_t)(((lid & 7) + ((lid >> 3) & 1) * 8) * SRA
                                      + (lid >> 4) * 16);

    float o[8][4];
#pragma unroll
    for (int j = 0; j < 8; j++)
#pragma unroll
        for (int e = 0; e < 4; e++) o[j][e] = 0.f;
    float m0 = -INFINITY, m1 = -INFINITY, l0 = 0.f, l1 = 0.f;

    const int NT = Sv / 64;
    for (int t = 0; t < NT; t++) {
        if (t + 1 < NT) { CP_ASYNC_WAIT(1); } else { CP_ASYNC_WAIT(0); }
        // fallback per-tile dep wait (only when deps weren't all ready at start)
        if (t + 2 < NT && tid == 0 && !s_ready) {
            const int mbl = (t + 2) >> 1;
            while (atomicAdd(&g_qkvf[(b * 16 + mbl) * 24 + 8 + nbh], 0) == 0)
                __nanosleep(100);
            while (atomicAdd(&g_qkvf[(b * 16 + mbl) * 24 + 16 + nbh], 0) == 0)
                __nanosleep(100);
        }
        __syncthreads();
        if (t + 2 < NT) LOADKV((t + 2) % 3, t + 2);

        const uint32_t kvb = smb + AS_KV + (t % 3) * (2 * KVTB);
        const uint32_t KB = kvb, VB = kvb + KVTB;

        // ---- S = Q K^T (log2-scaled via Q) ----
        float s[8][4];
#pragma unroll
        for (int j = 0; j < 8; j++)
#pragma unroll
            for (int e = 0; e < 4; e++) s[j][e] = 0.f;

#pragma unroll
        for (int kt = 0; kt < 4; kt++) {
            uint32_t aQ[4];
            ldsm_x4(smb + AS_Q + aoffQ + kt * 32, aQ);
#pragma unroll
            for (int gn = 0; gn < 4; gn++) {
                uint32_t bb[4];
                ldsm_x4(KB + boffK + gn * (16 * SRA) + kt * 32, bb);
                mma_f16(s[2 * gn],     aQ, bb[0], bb[1]);
                mma_f16(s[2 * gn + 1], aQ, bb[2], bb[3]);
            }
        }

        // ---- online softmax (log2 domain) ----
        const uint32_t msb = smb + AS_MS + (uint32_t)((t * 64 + 2 * (lid & 3)) * 4);
        float tm0 = -INFINITY, tm1 = -INFINITY;
#pragma unroll
        for (int j = 0; j < 8; j++) {
            float mkx, mky;
            asm("ld.shared.v2.f32 {%0,%1}, [%2];" : "=f"(mkx), "=f"(mky) : "r"(msb + j * 32));
            s[j][0] += mkx;
            s[j][1] += mky;
            s[j][2] += mkx;
            s[j][3] += mky;
            tm0 = fmaxf(tm0, fmaxf(s[j][0], s[j][1]));
            tm1 = fmaxf(tm1, fmaxf(s[j][2], s[j][3]));
        }
        tm0 = fmaxf(tm0, __shfl_xor_sync(0xffffffffu, tm0, 1));
        tm0 = fmaxf(tm0, __shfl_xor_sync(0xffffffffu, tm0, 2));
        tm1 = fmaxf(tm1, __shfl_xor_sync(0xffffffffu, tm1, 1));
        tm1 = fmaxf(tm1, __shfl_xor_sync(0xffffffffu, tm1, 2));

        float al0 = 1.f, al1 = 1.f;
        const bool need = (tm0 > m0) || (tm1 > m1);
        if (__any_sync(0xffffffffu, need)) {
            const float mn0 = fmaxf(m0, tm0), mn1 = fmaxf(m1, tm1);
            al0 = exp2f(m0 - mn0);
            al1 = exp2f(m1 - mn1);
            m0 = mn0; m1 = mn1;
#pragma unroll
            for (int j = 0; j < 8; j++) {
                o[j][0] *= al0; o[j][1] *= al0;
                o[j][2] *= al1; o[j][3] *= al1;
            }
        }

        float rs0 = 0.f, rs1 = 0.f;
#pragma unroll
        for (int j = 0; j < 8; j++) {
            s[j][0] = exp2f(s[j][0] - m0);
            s[j][1] = exp2f(s[j][1] - m0);
            s[j][2] = exp2f(s[j][2] - m1);
            s[j][3] = exp2f(s[j][3] - m1);
            rs0 += s[j][0] + s[j][1];
            rs1 += s[j][2] + s[j][3];
        }
        rs0 += __shfl_xor_sync(0xffffffffu, rs0, 1);
        rs0 += __shfl_xor_sync(0xffffffffu, rs0, 2);
        rs1 += __shfl_xor_sync(0xffffffffu, rs1, 1);
        rs1 += __shfl_xor_sync(0xffffffffu, rs1, 2);
        l0 = l0 * al0 + rs0;
        l1 = l1 * al1 + rs1;

        // ---- O += P V ----
#pragma unroll
        for (int kt = 0; kt < 4; kt++) {
            uint32_t ap[4];
            ap[0] = pack_h2(s[2 * kt][0],     s[2 * kt][1]);
            ap[1] = pack_h2(s[2 * kt][2],     s[2 * kt][3]);
            ap[2] = pack_h2(s[2 * kt + 1][0], s[2 * kt + 1][1]);
            ap[3] = pack_h2(s[2 * kt + 1][2], s[2 * kt + 1][3]);
#pragma unroll
            for (int jp = 0; jp < 4; jp++) {
                uint32_t bb[4];
                ldsm_x4_t(VB + voffV + kt * (16 * SRA) + jp * 32, bb);
                mma_f16(o[2 * jp],     ap, bb[0], bb[1]);
                mma_f16(o[2 * jp + 1], ap, bb[2], bb[3]);
            }
        }
    }

    // ---- Epilogue: normalize, store fp16 av; signal row-block ----
    const float inv0 = 1.f / l0, inv1 = 1.f / l1;
    const int rg = q0 + wq_ * 16 + (lid >> 2);
    const size_t obase = (rowbase + rg) * Hv + hd0 + 2 * (lid & 3);
#pragma unroll
    for (int j = 0; j < 8; j++) {
        *(uint32_t*)(av + obase + j * 8)          = pack_h2(o[j][0] * inv0, o[j][1] * inv0);
        *(uint32_t*)(av + obase + 8 * Hv + j * 8) = pack_h2(o[j][2] * inv1, o[j][3] * inv1);
    }

    __threadfence();
    __syncthreads();
    if (tid == 0) atomicAdd(&g_flags[b * 16 + qblk], 1);
}

// ============================================================================
// Launch — single kernel
// ============================================================================
extern "C" void kernel_launch(void* const* d_in, const int* in_sizes, int n_in,
                              void* d_out, int out_size)
{
    const float* x     = (const float*)d_in[0];
    const float* mask  = (const float*)d_in[1];
    const float* w_qkv = (const float*)d_in[2];
    const float* b_qkv = (const float*)d_in[3];
    const float* w_o   = (const float*)d_in[4];
    const float* b_o   = (const float*)d_in[5];
    float* out = (float*)d_out;

    cudaFuncSetAttribute(mega,
                         cudaFuncAttributeMaxDynamicSharedMemorySize, GSM_TOTAL);

    // ONE launch: cvt (512) + qkv (768) + attention (512) + proj (256)
    mega<<<2048, 256, GSM_TOTAL>>>(x, w_qkv, w_o, mask, b_qkv, b_o, out);
}

// round 14
// speedup vs baseline: 1.0167x; 1.0167x over previous
#include <cuda_runtime.h>
#include <cuda_fp16.h>
#include <math.h>
#include <stdint.h>

// Problem constants
#define Bv   2
#define Sv   2048
#define Hv   1024
#define NHv  16
#define HDv  64
#define H3   (3 * Hv)
#define MSEQ (Bv * Sv)          // 4096 rows

// softmax scale folded into Q and mask: (1/8) * log2(e)
#define QSCALE 0.18033688011112042f

// Scratch (device globals: allocation-guard safe)
__device__ __half g_x [(size_t)MSEQ * Hv];
__device__ __half g_wq[(size_t)H3 * Hv];
__device__ __half g_wo[(size_t)Hv * Hv];
__device__ __half g_qkv[(size_t)MSEQ * H3];
__device__ __half g_av[(size_t)MSEQ * Hv];
__device__ float  g_mask[Sv];            // mask * QSCALE
__device__ int    g_qkvf[768];           // per qkv 128x128 tile completion
__device__ int    g_flags[32];           // per 128-row-block attention completion
__device__ int    g_woc;                 // wo conversion block counter (0..64)

// ============================================================================
// Helpers
// ============================================================================
__device__ __forceinline__ uint32_t smem_to_u32(const void* smem_ptr) {
    uint32_t addr;
    asm("{ .reg .u64 tmp; cvta.to.shared.u64 tmp, %1; cvt.u32.u64 %0, tmp; }"
        : "=r"(addr) : "l"(smem_ptr));
    return addr;
}

__device__ __forceinline__ void ldsm_x4(uint32_t addr, uint32_t r[4]) {
    asm volatile("ldmatrix.sync.aligned.m8n8.x4.shared.b16 {%0,%1,%2,%3}, [%4];"
        : "=r"(r[0]), "=r"(r[1]), "=r"(r[2]), "=r"(r[3]) : "r"(addr));
}

__device__ __forceinline__ void ldsm_x4_t(uint32_t addr, uint32_t r[4]) {
    asm volatile("ldmatrix.sync.aligned.m8n8.x4.trans.shared.b16 {%0,%1,%2,%3}, [%4];"
        : "=r"(r[0]), "=r"(r[1]), "=r"(r[2]), "=r"(r[3]) : "r"(addr));
}

__device__ __forceinline__ void mma_f16(float d[4], const uint32_t a[4],
                                        uint32_t b0, uint32_t b1) {
    asm volatile(
        "mma.sync.aligned.m16n8k16.row.col.f32.f16.f16.f32 "
        "{%0,%1,%2,%3}, {%4,%5,%6,%7}, {%8,%9}, {%0,%1,%2,%3};"
        : "+f"(d[0]), "+f"(d[1]), "+f"(d[2]), "+f"(d[3])
        : "r"(a[0]), "r"(a[1]), "r"(a[2]), "r"(a[3]), "r"(b0), "r"(b1));
}

__device__ __forceinline__ uint32_t pack_h2(float x, float y) {
    __half2 h = __float22half2_rn(make_float2(x, y));
    return *(uint32_t*)&h;
}

#define CP_ASYNC16(dst_u32, src_ptr) \
    asm volatile("cp.async.cg.shared.global [%0], [%1], 16;" \
        :: "r"(dst_u32), "l"(src_ptr))
#define CP_ASYNC_COMMIT() asm volatile("cp.async.commit_group;" ::: "memory")
#define CP_ASYNC_WAIT(N)  asm volatile("cp.async.wait_group %0;" :: "n"(N) : "memory")

// ============================================================================
// Front-end cvt: x, wq (fp32->fp16, 2 float4/thread, fused 16B store),
// mask*QSCALE, and flag reset. High-occupancy standalone launch.
// ============================================================================
#define N4_X   (MSEQ * Hv / 4)        // 1048576 float4
#define N4_WQ  (H3 * Hv / 4)          // 786432 float4
#define NPAIRS ((N4_X + N4_WQ) / 2)   // 917504 thread-pairs

__global__ __launch_bounds__(256)
void cvt_front_kernel(const float* __restrict__ x, const float* __restrict__ wq,
                      const float* __restrict__ mask)
{
    const int i = blockIdx.x * blockDim.x + threadIdx.x;

    if (blockIdx.x == 0) {
        const int tid = threadIdx.x;
        if (tid < 128) {                 // mask: 512 floats = 128 float4
            float4 v = ((const float4*)mask)[tid];
            v.x *= QSCALE; v.y *= QSCALE; v.z *= QSCALE; v.w *= QSCALE;
            ((float4*)g_mask)[tid] = v;
        }
        // reset flags (runs before mega by launch order)
        if (tid < 32)  g_flags[tid] = 0;
        if (tid == 0)  g_woc = 0;
        for (int f = tid; f < 768; f += 256) g_qkvf[f] = 0;
    }

    if (i >= NPAIRS) return;
    const int j = i * 2;                 // first float4 index (even)
    const float* src;
    __half* dst;
    int jj;
    if (j < N4_X) { src = x;  dst = g_x;  jj = j; }
    else          { src = wq; dst = g_wq; jj = j - N4_X; }
    float4 v0 = ((const float4*)src)[jj];
    float4 v1 = ((const float4*)src)[jj + 1];
    uint4 o;
    o.x = pack_h2(v0.x, v0.y);
    o.y = pack_h2(v0.z, v0.w);
    o.z = pack_h2(v1.x, v1.y);
    o.w = pack_h2(v1.z, v1.w);
    *(uint4*)(dst + (size_t)jj * 4) = o;
}

// ============================================================================
// fp16 GEMM (NT) device body: CTA 128x128, KC=64, 3-stage cp.async pipeline.
// ============================================================================
#define SRB   144
#define MATB  (128 * SRB)
#define STGB  (2 * MATB)
#define GSM_TOTAL (3 * STGB)     // 110592 B

template<int OUT_HALF>
__device__ __forceinline__
void gemm_body(char* smem, const __half* __restrict__ A, const __half* __restrict__ W,
               const float* __restrict__ bias, float* __restrict__ C,
               __half* __restrict__ Ch, int M, int N, int K, int m0, int n0)
{
    const uint32_t smb = smem_to_u32(smem);
    const int tid = threadIdx.x;
    const int lid = tid & 31;
    const int wid = tid >> 5;
    const int wm  = wid & 3;
    const int wn  = wid >> 2;

    const uint32_t aoff = (uint32_t)((wm * 32 + (lid & 7) + ((lid >> 3) & 1) * 8) * SRB
                                     + (lid >> 4) * 16);
    const uint32_t boff = (uint32_t)((wn * 64 + (lid & 7) + (lid >> 4) * 8) * SRB
                                     + ((lid >> 3) & 1) * 16);

    float acc[2][8][4];
#pragma unroll
    for (int i = 0; i < 2; i++)
#pragma unroll
        for (int j = 0; j < 8; j++)
#pragma unroll
            for (int e = 0; e < 4; e++) acc[i][j][e] = 0.f;

    auto LOAD = [&](int buf, int chunk) {
        const uint32_t base = smb + buf * STGB;
        const int k0 = chunk * 64;
#pragma unroll
        for (int i = 0; i < 8; i++) {
            int idx = tid + i * 256;
            int mat = idx >> 10;
            int rem = idx & 1023;
            int r = rem >> 3;
            int c = rem & 7;
            const __half* src = mat
                ? W + (size_t)(n0 + r) * K + k0 + c * 8
                : A + (size_t)(m0 + r) * K + k0 + c * 8;
            CP_ASYNC16(base + (uint32_t)(mat * MATB + r * SRB + c * 16), src);
        }
        CP_ASYNC_COMMIT();
    };

    auto MMA = [&](int buf) {
        const uint32_t base = smb + buf * STGB;
#pragma unroll
        for (int kt = 0; kt < 4; kt++) {
            uint32_t a0[4], a1[4];
            ldsm_x4(base + aoff + kt * 32, a0);
            ldsm_x4(base + aoff + 16 * SRB + kt * 32, a1);
#pragma unroll
            for (int gn = 0; gn < 4; gn++) {
                uint32_t bb[4];
                ldsm_x4(base + MATB + boff + gn * (16 * SRB) + kt * 32, bb);
                mma_f16(acc[0][2 * gn],     a0, bb[0], bb[1]);
                mma_f16(acc[0][2 * gn + 1], a0, bb[2], bb[3]);
                mma_f16(acc[1][2 * gn],     a1, bb[0], bb[1]);
                mma_f16(acc[1][2 * gn + 1], a1, bb[2], bb[3]);
            }
        }
    };

    const int NCHUNK = K / 64;
    LOAD(0, 0);
    LOAD(1, 1);

    for (int i = 0; i < NCHUNK; i++) {
        if (i + 1 < NCHUNK) { CP_ASYNC_WAIT(1); } else { CP_ASYNC_WAIT(0); }
        __syncthreads();
        if (i + 2 < NCHUNK) LOAD((i + 2) % 3, i + 2);
        MMA(i % 3);
    }

#pragma unroll
    for (int mt = 0; mt < 2; mt++) {
        const int row = m0 + wm * 32 + mt * 16 + (lid >> 2);
#pragma unroll
        for (int nt = 0; nt < 8; nt++) {
            const int col = n0 + wn * 64 + nt * 8 + (lid & 3) * 2;
            const float b0 = bias[col], b1 = bias[col + 1];
            float v00 = acc[mt][nt][0] + b0, v01 = acc[mt][nt][1] + b1;
            float v10 = acc[mt][nt][2] + b0, v11 = acc[mt][nt][3] + b1;
            if (OUT_HALF) {
                const float sc = (col < Hv) ? QSCALE : 1.0f;
                v00 *= sc; v01 *= sc; v10 *= sc; v11 *= sc;
                *(uint32_t*)(Ch + (size_t)row * N + col)       = pack_h2(v00, v01);
                *(uint32_t*)(Ch + (size_t)(row + 8) * N + col) = pack_h2(v10, v11);
            } else {
                *(float2*)(C + (size_t)row * N + col)       = make_float2(v00, v01);
                *(float2*)(C + (size_t)(row + 8) * N + col) = make_float2(v10, v11);
            }
        }
    }
}

// ============================================================================
// MEGA kernel: wo-cvt (bids 0..63) + qkv GEMM (64..831) + attention (832..1343)
// + output projection (1344..1599). Deps strictly backward in bid order.
// ============================================================================
#define SRA   144
#define QTB   (128 * SRA)
#define KVTB  (64 * SRA)
#define AS_Q  0
#define AS_KV QTB
#define AS_MS (AS_KV + 3 * 2 * KVTB)

__global__ __launch_bounds__(256, 2)
void mega(const float* __restrict__ xf /*unused*/, const float* __restrict__ wqf /*unused*/,
          const float* __restrict__ wof, const float* __restrict__ b_qkv,
          const float* __restrict__ b_o, float* __restrict__ out)
{
    extern __shared__ char smem[];
    const int tid = threadIdx.x;
    const int bid = blockIdx.x;

    __half* x   = g_x;
    __half* wq  = g_wq;
    __half* wo  = g_wo;
    __half* qkv = g_qkv;
    __half* av  = g_av;

    if (bid < 64) {
        // --------------------- wo conversion block (fast) ---------------------
        // wo = 1024x1024 fp32 = 262144 float4; 64 blocks x 2048 pairs
        const int base = bid * 2048 + tid;    // pair index
#pragma unroll
        for (int l = 0; l < 8; l++) {
            int p = base + l * 256;
            int j = p * 2;
            float4 v0 = ((const float4*)wof)[j];
            float4 v1 = ((const float4*)wof)[j + 1];
            uint4 o;
            o.x = pack_h2(v0.x, v0.y);
            o.y = pack_h2(v0.z, v0.w);
            o.z = pack_h2(v1.x, v1.y);
            o.w = pack_h2(v1.z, v1.w);
            *(uint4*)(wo + (size_t)j * 4) = o;
        }
        __threadfence();
        __syncthreads();
        if (tid == 0) atomicAdd(&g_woc, 1);
        return;
    }

    if (bid < 832) {
        // ----------------------- QKV projection tile -----------------------
        const int idx = bid - 64;
        const int mb = idx / 24, nb = idx % 24;
        gemm_body<1>(smem, x, wq, b_qkv, nullptr, qkv, MSEQ, H3, Hv,
                     mb * 128, nb * 128);
        __threadfence();
        __syncthreads();
        if (tid == 0) atomicExch(&g_qkvf[idx], 1);
        return;
    }

    if (bid >= 1344) {
        // ----------------------- output projection tile --------------------
        const int idx = bid - 1344;
        const int mb  = idx >> 3;
        const int n0  = (idx & 7) * 128;
        if (tid == 0) {
            while (atomicAdd(&g_woc, 0) < 64) __nanosleep(200);
            while (atomicAdd(&g_flags[mb], 0) < NHv) __nanosleep(200);
        }
        __syncthreads();
        gemm_body<0>(smem, av, wo, b_o, out, nullptr, MSEQ, Hv, Hv,
                     mb * 128, n0);
        return;
    }

    // --------------------------- attention path ---------------------------
    const uint32_t smb = smem_to_u32(smem);
    const int abid = bid - 832;
    const int lid = tid & 31;
    const int wq_ = tid >> 5;
    const int qblk = abid & 15;
    const int q0  = qblk * 128;
    const int h   = (abid >> 4) & 15;
    const int b   = abid >> 8;
    const size_t rowbase = (size_t)b * Sv;
    const int hd0 = h * HDv;

    // qkv tile flag indices this CTA depends on
    const int nbh = h >> 1;
    const int fq  = (b * 16 + qblk) * 24 + nbh;             // Q tile
    __shared__ int s_ready;   // 1 = all deps satisfied at CTA start
    if (tid == 0) s_ready = 1;
    __syncthreads();
    if (tid < 33) {
        int f;
        if (tid == 32)      f = fq;
        else if (tid < 16)  f = (b * 16 + tid) * 24 + 8 + nbh;
        else                f = (b * 16 + (tid - 16)) * 24 + 16 + nbh;
        if (atomicAdd(&g_qkvf[f], 0) == 0) atomicExch(&s_ready, 0);
    }
    __syncthreads();
    if (tid == 0 && !s_ready) {
        // wait for Q + K/V tiles 0,1 (rows 0..127 -> local mb 0)
        while (atomicAdd(&g_qkvf[fq], 0) == 0) __nanosleep(100);
        while (atomicAdd(&g_qkvf[b * 384 + 8 + nbh], 0) == 0) __nanosleep(100);
        while (atomicAdd(&g_qkvf[b * 384 + 16 + nbh], 0) == 0) __nanosleep(100);
    }
    __syncthreads();

    auto LOADKV = [&](int buf, int tile) {
        const int kb = tile * 64;
        const uint32_t kvb = smb + AS_KV + buf * (2 * KVTB);
#pragma unroll
        for (int i = 0; i < 4; i++) {
            int idx = tid + i * 256;
            int mat = idx >> 9;
            int rem = idx & 511;
            int r = rem >> 3, c = rem & 7;
            int off = mat ? 2 * Hv : Hv;
            CP_ASYNC16(kvb + mat * KVTB + r * SRA + c * 16,
                       qkv + (rowbase + kb + r) * H3 + off + hd0 + c * 8);
        }
        CP_ASYNC_COMMIT();
    };

    // group 0: mask + Q + KV tile 0; group 1: KV tile 1
#pragma unroll
    for (int i = 0; i < 2; i++) {
        int idx = tid + i * 256;
        CP_ASYNC16(smb + AS_MS + idx * 16, g_mask + idx * 4);
    }
#pragma unroll
    for (int i = 0; i < 4; i++) {
        int idx = tid + i * 256;
        int r = idx >> 3, c = idx & 7;
        CP_ASYNC16(smb + AS_Q + r * SRA + c * 16,
                   qkv + (rowbase + q0 + r) * H3 + hd0 + c * 8);
    }
    {
        const uint32_t kvb = smb + AS_KV;
#pragma unroll
        for (int i = 0; i < 4; i++) {
            int idx = tid + i * 256;
            int mat = idx >> 9;
            int rem = idx & 511;
            int r = rem >> 3, c = rem & 7;
            int off = mat ? 2 * Hv : Hv;
            CP_ASYNC16(kvb + mat * KVTB + r * SRA + c * 16,
                       qkv + (rowbase + r) * H3 + off + hd0 + c * 8);
        }
        CP_ASYNC_COMMIT();
    }
    LOADKV(1, 1);

    const uint32_t aoffQ = (uint32_t)((wq_ * 16 + (lid & 7) + ((lid >> 3) & 1) * 8) * SRA
                                      + (lid >> 4) * 16);
    const uint32_t boffK = (uint32_t)(((lid & 7) + (lid >> 4) * 8) * SRA
                                      + ((lid >> 3) & 1) * 16);
    const uint32_t voffV = (uint32_t)(((lid & 7) + ((lid >> 3) & 1) * 8) * SRA
                                      + (lid >> 4) * 16);

    float o[8][4];
#pragma unroll
    for (int j = 0; j < 8; j++)
#pragma unroll
        for (int e = 0; e < 4; e++) o[j][e] = 0.f;
    float m0 = -INFINITY, m1 = -INFINITY, l0 = 0.f, l1 = 0.f;

    const int NT = Sv / 64;
    for (int t = 0; t < NT; t++) {
        if (t + 1 < NT) { CP_ASYNC_WAIT(1); } else { CP_ASYNC_WAIT(0); }
        // fallback per-tile dep wait (only when deps weren't all ready at start)
        if (t + 2 < NT && tid == 0 && !s_ready) {
            const int mbl = (t + 2) >> 1;
            while (atomicAdd(&g_qkvf[(b * 16 + mbl) * 24 + 8 + nbh], 0) == 0)
                __nanosleep(100);
            while (atomicAdd(&g_qkvf[(b * 16 + mbl) * 24 + 16 + nbh], 0) == 0)
                __nanosleep(100);
        }
        __syncthreads();
        if (t + 2 < NT) LOADKV((t + 2) % 3, t + 2);

        const uint32_t kvb = smb + AS_KV + (t % 3) * (2 * KVTB);
        const uint32_t KB = kvb, VB = kvb + KVTB;

        // ---- S = Q K^T (log2-scaled via Q) ----
        float s[8][4];
#pragma unroll
        for (int j = 0; j < 8; j++)
#pragma unroll
            for (int e = 0; e < 4; e++) s[j][e] = 0.f;

#pragma unroll
        for (int kt = 0; kt < 4; kt++) {
            uint32_t aQ[4];
            ldsm_x4(smb + AS_Q + aoffQ + kt * 32, aQ);
#pragma unroll
            for (int gn = 0; gn < 4; gn++) {
                uint32_t bb[4];
                ldsm_x4(KB + boffK + gn * (16 * SRA) + kt * 32, bb);
                mma_f16(s[2 * gn],     aQ, bb[0], bb[1]);
                mma_f16(s[2 * gn + 1], aQ, bb[2], bb[3]);
            }
        }

        // ---- online softmax (log2 domain) ----
        const uint32_t msb = smb + AS_MS + (uint32_t)((t * 64 + 2 * (lid & 3)) * 4);
        float tm0 = -INFINITY, tm1 = -INFINITY;
#pragma unroll
        for (int j = 0; j < 8; j++) {
            float mkx, mky;
            asm("ld.shared.v2.f32 {%0,%1}, [%2];" : "=f"(mkx), "=f"(mky) : "r"(msb + j * 32));
            s[j][0] += mkx;
            s[j][1] += mky;
            s[j][2] += mkx;
            s[j][3] += mky;
            tm0 = fmaxf(tm0, fmaxf(s[j][0], s[j][1]));
            tm1 = fmaxf(tm1, fmaxf(s[j][2], s[j][3]));
        }
        tm0 = fmaxf(tm0, __shfl_xor_sync(0xffffffffu, tm0, 1));
        tm0 = fmaxf(tm0, __shfl_xor_sync(0xffffffffu, tm0, 2));
        tm1 = fmaxf(tm1, __shfl_xor_sync(0xffffffffu, tm1, 1));
        tm1 = fmaxf(tm1, __shfl_xor_sync(0xffffffffu, tm1, 2));

        float al0 = 1.f, al1 = 1.f;
        const bool need = (tm0 > m0) || (tm1 > m1);
        if (__any_sync(0xffffffffu, need)) {
            const float mn0 = fmaxf(m0, tm0), mn1 = fmaxf(m1, tm1);
            al0 = exp2f(m0 - mn0);
            al1 = exp2f(m1 - mn1);
            m0 = mn0; m1 = mn1;
#pragma unroll
            for (int j = 0; j < 8; j++) {
                o[j][0] *= al0; o[j][1] *= al0;
                o[j][2] *= al1; o[j][3] *= al1;
            }
        }

        float rs0 = 0.f, rs1 = 0.f;
#pragma unroll
        for (int j = 0; j < 8; j++) {
            s[j][0] = exp2f(s[j][0] - m0);
            s[j][1] = exp2f(s[j][1] - m0);
            s[j][2] = exp2f(s[j][2] - m1);
            s[j][3] = exp2f(s[j][3] - m1);
            rs0 += s[j][0] + s[j][1];
            rs1 += s[j][2] + s[j][3];
        }
        rs0 += __shfl_xor_sync(0xffffffffu, rs0, 1);
        rs0 += __shfl_xor_sync(0xffffffffu, rs0, 2);
        rs1 += __shfl_xor_sync(0xffffffffu, rs1, 1);
        rs1 += __shfl_xor_sync(0xffffffffu, rs1, 2);
        l0 = l0 * al0 + rs0;
        l1 = l1 * al1 + rs1;

        // ---- O += P V ----
#pragma unroll
        for (int kt = 0; kt < 4; kt++) {
            uint32_t ap[4];
            ap[0] = pack_h2(s[2 * kt][0],     s[2 * kt][1]);
            ap[1] = pack_h2(s[2 * kt][2],     s[2 * kt][3]);
            ap[2] = pack_h2(s[2 * kt + 1][0], s[2 * kt + 1][1]);
            ap[3] = pack_h2(s[2 * kt + 1][2], s[2 * kt + 1][3]);
#pragma unroll
            for (int jp = 0; jp < 4; jp++) {
                uint32_t bb[4];
                ldsm_x4_t(VB + voffV + kt * (16 * SRA) + jp * 32, bb);
                mma_f16(o[2 * jp],     ap, bb[0], bb[1]);
                mma_f16(o[2 * jp + 1], ap, bb[2], bb[3]);
            }
        }
    }

    // ---- Epilogue: normalize, store fp16 av; signal row-block ----
    const float inv0 = 1.f / l0, inv1 = 1.f / l1;
    const int rg = q0 + wq_ * 16 + (lid >> 2);
    const size_t obase = (rowbase + rg) * Hv + hd0 + 2 * (lid & 3);
#pragma unroll
    for (int j = 0; j < 8; j++) {
        *(uint32_t*)(av + obase + j * 8)          = pack_h2(o[j][0] * inv0, o[j][1] * inv0);
        *(uint32_t*)(av + obase + 8 * Hv + j * 8) = pack_h2(o[j][2] * inv1, o[j][3] * inv1);
    }

    __threadfence();
    __syncthreads();
    if (tid == 0) atomicAdd(&g_flags[b * 16 + qblk], 1);
}

// ============================================================================
// Launch
// ============================================================================
extern "C" void kernel_launch(void* const* d_in, const int* in_sizes, int n_in,
                              void* d_out, int out_size)
{
    const float* x     = (const float*)d_in[0];
    const float* mask  = (const float*)d_in[1];
    const float* w_qkv = (const float*)d_in[2];
    const float* b_qkv = (const float*)d_in[3];
    const float* w_o   = (const float*)d_in[4];
    const float* b_o   = (const float*)d_in[5];
    float* out = (float*)d_out;

    cudaFuncSetAttribute(mega,
                         cudaFuncAttributeMaxDynamicSharedMemorySize, GSM_TOTAL);

    // 0) Front-end: x/wq -> fp16 (2x float4 per thread), mask scale, flag reset
    cvt_front_kernel<<<(NPAIRS + 255) / 256, 256>>>(x, w_qkv, mask);

    // 1) Mega: wo-cvt (64) + qkv (768) + attention (512) + proj (256)
    mega<<<1600, 256, GSM_TOTAL>>>(x, w_qkv, w_o, b_qkv, b_o, out);
}

// round 15
// speedup vs baseline: 1.0192x; 1.0024x over previous
#include <cuda_runtime.h>
#include <cuda_fp16.h>
#include <math.h>
#include <stdint.h>

// Problem constants
#define Bv   2
#define Sv   2048
#define Hv   1024
#define NHv  16
#define HDv  64
#define H3   (3 * Hv)
#define MSEQ (Bv * Sv)          // 4096 rows

// softmax scale folded into Q and mask: (1/8) * log2(e)
#define QSCALE 0.18033688011112042f

// Scratch (device globals: allocation-guard safe)
__device__ __half g_x [(size_t)MSEQ * Hv];
__device__ __half g_wq[(size_t)H3 * Hv];
__device__ __half g_wo[(size_t)Hv * Hv];
__device__ __half g_qkv[(size_t)MSEQ * H3];
__device__ __half g_av[(size_t)MSEQ * Hv];
__device__ float  g_mask[Sv];            // mask * QSCALE
__device__ int    g_qkvf[768];           // per qkv 128x128 tile completion (mb*24+nb)
__device__ int    g_flags[32];           // per 128-row-block attention completion
__device__ int    g_woc;                 // wo conversion block counter (0..64)

// ============================================================================
// Helpers
// ============================================================================
__device__ __forceinline__ uint32_t smem_to_u32(const void* smem_ptr) {
    uint32_t addr;
    asm("{ .reg .u64 tmp; cvta.to.shared.u64 tmp, %1; cvt.u32.u64 %0, tmp; }"
        : "=r"(addr) : "l"(smem_ptr));
    return addr;
}

__device__ __forceinline__ void ldsm_x4(uint32_t addr, uint32_t r[4]) {
    asm volatile("ldmatrix.sync.aligned.m8n8.x4.shared.b16 {%0,%1,%2,%3}, [%4];"
        : "=r"(r[0]), "=r"(r[1]), "=r"(r[2]), "=r"(r[3]) : "r"(addr));
}

__device__ __forceinline__ void ldsm_x4_t(uint32_t addr, uint32_t r[4]) {
    asm volatile("ldmatrix.sync.aligned.m8n8.x4.trans.shared.b16 {%0,%1,%2,%3}, [%4];"
        : "=r"(r[0]), "=r"(r[1]), "=r"(r[2]), "=r"(r[3]) : "r"(addr));
}

__device__ __forceinline__ void mma_f16(float d[4], const uint32_t a[4],
                                        uint32_t b0, uint32_t b1) {
    asm volatile(
        "mma.sync.aligned.m16n8k16.row.col.f32.f16.f16.f32 "
        "{%0,%1,%2,%3}, {%4,%5,%6,%7}, {%8,%9}, {%0,%1,%2,%3};"
        : "+f"(d[0]), "+f"(d[1]), "+f"(d[2]), "+f"(d[3])
        : "r"(a[0]), "r"(a[1]), "r"(a[2]), "r"(a[3]), "r"(b0), "r"(b1));
}

__device__ __forceinline__ uint32_t pack_h2(float x, float y) {
    __half2 h = __float22half2_rn(make_float2(x, y));
    return *(uint32_t*)&h;
}

#define CP_ASYNC16(dst_u32, src_ptr) \
    asm volatile("cp.async.cg.shared.global [%0], [%1], 16;" \
        :: "r"(dst_u32), "l"(src_ptr))
#define CP_ASYNC_COMMIT() asm volatile("cp.async.commit_group;" ::: "memory")
#define CP_ASYNC_WAIT(N)  asm volatile("cp.async.wait_group %0;" :: "n"(N) : "memory")

// ============================================================================
// Front-end cvt: x, wq (fp32->fp16, 2 float4/thread, fused 16B store),
// mask*QSCALE, and flag reset. High-occupancy standalone launch.
// ============================================================================
#define N4_X   (MSEQ * Hv / 4)        // 1048576 float4
#define N4_WQ  (H3 * Hv / 4)          // 786432 float4
#define NPAIRS ((N4_X + N4_WQ) / 2)   // 917504 thread-pairs

__global__ __launch_bounds__(256)
void cvt_front_kernel(const float* __restrict__ x, const float* __restrict__ wq,
                      const float* __restrict__ mask)
{
    const int i = blockIdx.x * blockDim.x + threadIdx.x;

    if (blockIdx.x == 0) {
        const int tid = threadIdx.x;
        if (tid < 128) {                 // mask: 512 floats = 128 float4
            float4 v = ((const float4*)mask)[tid];
            v.x *= QSCALE; v.y *= QSCALE; v.z *= QSCALE; v.w *= QSCALE;
            ((float4*)g_mask)[tid] = v;
        }
        // reset flags (runs before mega by launch order)
        if (tid < 32)  g_flags[tid] = 0;
        if (tid == 0)  g_woc = 0;
        for (int f = tid; f < 768; f += 256) g_qkvf[f] = 0;
    }

    if (i >= NPAIRS) return;
    const int j = i * 2;                 // first float4 index (even)
    const float* src;
    __half* dst;
    int jj;
    if (j < N4_X) { src = x;  dst = g_x;  jj = j; }
    else          { src = wq; dst = g_wq; jj = j - N4_X; }
    float4 v0 = ((const float4*)src)[jj];
    float4 v1 = ((const float4*)src)[jj + 1];
    uint4 o;
    o.x = pack_h2(v0.x, v0.y);
    o.y = pack_h2(v0.z, v0.w);
    o.z = pack_h2(v1.x, v1.y);
    o.w = pack_h2(v1.z, v1.w);
    *(uint4*)(dst + (size_t)jj * 4) = o;
}

// ============================================================================
// fp16 GEMM (NT) device body: CTA 128x128, KC=64, 3-stage cp.async pipeline.
// ============================================================================
#define SRB   144
#define MATB  (128 * SRB)
#define STGB  (2 * MATB)
#define GSM_TOTAL (3 * STGB)     // 110592 B

template<int OUT_HALF>
__device__ __forceinline__
void gemm_body(char* smem, const __half* __restrict__ A, const __half* __restrict__ W,
               const float* __restrict__ bias, float* __restrict__ C,
               __half* __restrict__ Ch, int M, int N, int K, int m0, int n0)
{
    const uint32_t smb = smem_to_u32(smem);
    const int tid = threadIdx.x;
    const int lid = tid & 31;
    const int wid = tid >> 5;
    const int wm  = wid & 3;
    const int wn  = wid >> 2;

    const uint32_t aoff = (uint32_t)((wm * 32 + (lid & 7) + ((lid >> 3) & 1) * 8) * SRB
                                     + (lid >> 4) * 16);
    const uint32_t boff = (uint32_t)((wn * 64 + (lid & 7) + (lid >> 4) * 8) * SRB
                                     + ((lid >> 3) & 1) * 16);

    float acc[2][8][4];
#pragma unroll
    for (int i = 0; i < 2; i++)
#pragma unroll
        for (int j = 0; j < 8; j++)
#pragma unroll
            for (int e = 0; e < 4; e++) acc[i][j][e] = 0.f;

    auto LOAD = [&](int buf, int chunk) {
        const uint32_t base = smb + buf * STGB;
        const int k0 = chunk * 64;
#pragma unroll
        for (int i = 0; i < 8; i++) {
            int idx = tid + i * 256;
            int mat = idx >> 10;
            int rem = idx & 1023;
            int r = rem >> 3;
            int c = rem & 7;
            const __half* src = mat
                ? W + (size_t)(n0 + r) * K + k0 + c * 8
                : A + (size_t)(m0 + r) * K + k0 + c * 8;
            CP_ASYNC16(base + (uint32_t)(mat * MATB + r * SRB + c * 16), src);
        }
        CP_ASYNC_COMMIT();
    };

    auto MMA = [&](int buf) {
        const uint32_t base = smb + buf * STGB;
#pragma unroll
        for (int kt = 0; kt < 4; kt++) {
            uint32_t a0[4], a1[4];
            ldsm_x4(base + aoff + kt * 32, a0);
            ldsm_x4(base + aoff + 16 * SRB + kt * 32, a1);
#pragma unroll
            for (int gn = 0; gn < 4; gn++) {
                uint32_t bb[4];
                ldsm_x4(base + MATB + boff + gn * (16 * SRB) + kt * 32, bb);
                mma_f16(acc[0][2 * gn],     a0, bb[0], bb[1]);
                mma_f16(acc[0][2 * gn + 1], a0, bb[2], bb[3]);
                mma_f16(acc[1][2 * gn],     a1, bb[0], bb[1]);
                mma_f16(acc[1][2 * gn + 1], a1, bb[2], bb[3]);
            }
        }
    };

    const int NCHUNK = K / 64;
    LOAD(0, 0);
    LOAD(1, 1);

    for (int i = 0; i < NCHUNK; i++) {
        if (i + 1 < NCHUNK) { CP_ASYNC_WAIT(1); } else { CP_ASYNC_WAIT(0); }
        __syncthreads();
        if (i + 2 < NCHUNK) LOAD((i + 2) % 3, i + 2);
        MMA(i % 3);
    }

#pragma unroll
    for (int mt = 0; mt < 2; mt++) {
        const int row = m0 + wm * 32 + mt * 16 + (lid >> 2);
#pragma unroll
        for (int nt = 0; nt < 8; nt++) {
            const int col = n0 + wn * 64 + nt * 8 + (lid & 3) * 2;
            const float b0 = bias[col], b1 = bias[col + 1];
            float v00 = acc[mt][nt][0] + b0, v01 = acc[mt][nt][1] + b1;
            float v10 = acc[mt][nt][2] + b0, v11 = acc[mt][nt][3] + b1;
            if (OUT_HALF) {
                const float sc = (col < Hv) ? QSCALE : 1.0f;
                v00 *= sc; v01 *= sc; v10 *= sc; v11 *= sc;
                *(uint32_t*)(Ch + (size_t)row * N + col)       = pack_h2(v00, v01);
                *(uint32_t*)(Ch + (size_t)(row + 8) * N + col) = pack_h2(v10, v11);
            } else {
                *(float2*)(C + (size_t)row * N + col)       = make_float2(v00, v01);
                *(float2*)(C + (size_t)(row + 8) * N + col) = make_float2(v10, v11);
            }
        }
    }
}

// ============================================================================
// MEGA kernel: wo-cvt (bids 0..63) + qkv GEMM (64..831, head-pair-interleaved
// ordering) + attention (832..1343) + output projection (1344..1599).
// Deps strictly backward in bid order.
// ============================================================================
#define SRA   144
#define QTB   (128 * SRA)
#define KVTB  (64 * SRA)
#define AS_Q  0
#define AS_KV QTB
#define AS_MS (AS_KV + 3 * 2 * KVTB)

__global__ __launch_bounds__(256, 2)
void mega(const float* __restrict__ xf /*unused*/, const float* __restrict__ wqf /*unused*/,
          const float* __restrict__ wof, const float* __restrict__ b_qkv,
          const float* __restrict__ b_o, float* __restrict__ out)
{
    extern __shared__ char smem[];
    const int tid = threadIdx.x;
    const int bid = blockIdx.x;

    __half* x   = g_x;
    __half* wq  = g_wq;
    __half* wo  = g_wo;
    __half* qkv = g_qkv;
    __half* av  = g_av;

    if (bid < 64) {
        // --------------------- wo conversion block (fast) ---------------------
        const int base = bid * 2048 + tid;    // pair index
#pragma unroll
        for (int l = 0; l < 8; l++) {
            int p = base + l * 256;
            int j = p * 2;
            float4 v0 = ((const float4*)wof)[j];
            float4 v1 = ((const float4*)wof)[j + 1];
            uint4 o;
            o.x = pack_h2(v0.x, v0.y);
            o.y = pack_h2(v0.z, v0.w);
            o.z = pack_h2(v1.x, v1.y);
            o.w = pack_h2(v1.z, v1.w);
            *(uint4*)(wo + (size_t)j * 4) = o;
        }
        __threadfence();
        __syncthreads();
        if (tid == 0) atomicAdd(&g_woc, 1);
        return;
    }

    if (bid < 832) {
        // ----------------------- QKV projection tile -----------------------
        // Head-pair-interleaved ordering: group g = head-pair; within group,
        // all 32 mb of Q(nb=g), then K(nb=8+g), then V(nb=16+g). After 96
        // tiles, heads 2g/2g+1 attention deps are fully ready (both batches).
        const int idx = bid - 64;
        const int grp = idx / 96;             // 0..7 (head pair)
        const int sub = idx % 96;
        const int phase = sub >> 5;           // 0=Q, 1=K, 2=V
        const int mb  = sub & 31;
        const int nb  = phase == 0 ? grp : (phase == 1 ? 8 + grp : 16 + grp);
        gemm_body<1>(smem, x, wq, b_qkv, nullptr, qkv, MSEQ, H3, Hv,
                     mb * 128, nb * 128);
        __threadfence();
        __syncthreads();
        if (tid == 0) atomicExch(&g_qkvf[mb * 24 + nb], 1);
        return;
    }

    if (bid >= 1344) {
        // ----------------------- output projection tile --------------------
        const int idx = bid - 1344;
        const int mb  = idx >> 3;
        const int n0  = (idx & 7) * 128;
        if (tid == 0) {
            while (atomicAdd(&g_woc, 0) < 64) __nanosleep(200);
            while (atomicAdd(&g_flags[mb], 0) < NHv) __nanosleep(200);
        }
        __syncthreads();
        gemm_body<0>(smem, av, wo, b_o, out, nullptr, MSEQ, Hv, Hv,
                     mb * 128, n0);
        return;
    }

    // --------------------------- attention path ---------------------------
    const uint32_t smb = smem_to_u32(smem);
    const int abid = bid - 832;
    const int lid = tid & 31;
    const int wq_ = tid >> 5;
    const int qblk = abid & 15;
    const int q0  = qblk * 128;
    const int h   = (abid >> 4) & 15;
    const int b   = abid >> 8;
    const size_t rowbase = (size_t)b * Sv;
    const int hd0 = h * HDv;

    // qkv tile flag indices this CTA depends on
    const int nbh = h >> 1;
    const int fq  = (b * 16 + qblk) * 24 + nbh;             // Q tile
    __shared__ int s_ready;   // 1 = all deps satisfied at CTA start
    if (tid == 0) s_ready = 1;
    __syncthreads();
    if (tid < 33) {
        int f;
        if (tid == 32)      f = fq;
        else if (tid < 16)  f = (b * 16 + tid) * 24 + 8 + nbh;
        else                f = (b * 16 + (tid - 16)) * 24 + 16 + nbh;
        if (atomicAdd(&g_qkvf[f], 0) == 0) atomicExch(&s_ready, 0);
    }
    __syncthreads();
    if (tid == 0 && !s_ready) {
        // wait for Q + K/V tiles 0,1 (rows 0..127 -> local mb 0)
        while (atomicAdd(&g_qkvf[fq], 0) == 0) __nanosleep(100);
        while (atomicAdd(&g_qkvf[b * 384 + 8 + nbh], 0) == 0) __nanosleep(100);
        while (atomicAdd(&g_qkvf[b * 384 + 16 + nbh], 0) == 0) __nanosleep(100);
    }
    __syncthreads();

    auto LOADKV = [&](int buf, int tile) {
        const int kb = tile * 64;
        const uint32_t kvb = smb + AS_KV + buf * (2 * KVTB);
#pragma unroll
        for (int i = 0; i < 4; i++) {
            int idx = tid + i * 256;
            int mat = idx >> 9;
            int rem = idx & 511;
            int r = rem >> 3, c = rem & 7;
            int off = mat ? 2 * Hv : Hv;
            CP_ASYNC16(kvb + mat * KVTB + r * SRA + c * 16,
                       qkv + (rowbase + kb + r) * H3 + off + hd0 + c * 8);
        }
        CP_ASYNC_COMMIT();
    };

    // group 0: mask + Q + KV tile 0; group 1: KV tile 1
#pragma unroll
    for (int i = 0; i < 2; i++) {
        int idx = tid + i * 256;
        CP_ASYNC16(smb + AS_MS + idx * 16, g_mask + idx * 4);
    }
#pragma unroll
    for (int i = 0; i < 4; i++) {
        int idx = tid + i * 256;
        int r = idx >> 3, c = idx & 7;
        CP_ASYNC16(smb + AS_Q + r * SRA + c * 16,
                   qkv + (rowbase + q0 + r) * H3 + hd0 + c * 8);
    }
    {
        const uint32_t kvb = smb + AS_KV;
#pragma unroll
        for (int i = 0; i < 4; i++) {
            int idx = tid + i * 256;
            int mat = idx >> 9;
            int rem = idx & 511;
            int r = rem >> 3, c = rem & 7;
            int off = mat ? 2 * Hv : Hv;
            CP_ASYNC16(kvb + mat * KVTB + r * SRA + c * 16,
                       qkv + (rowbase + r) * H3 + off + hd0 + c * 8);
        }
        CP_ASYNC_COMMIT();
    }
    LOADKV(1, 1);

    const uint32_t aoffQ = (uint32_t)((wq_ * 16 + (lid & 7) + ((lid >> 3) & 1) * 8) * SRA
                                      + (lid >> 4) * 16);
    const uint32_t boffK = (uint32_t)(((lid & 7) + (lid >> 4) * 8) * SRA
                                      + ((lid >> 3) & 1) * 16);
    const uint32_t voffV = (uint32_t)(((lid & 7) + ((lid >> 3) & 1) * 8) * SRA
                                      + (lid >> 4) * 16);

    float o[8][4];
#pragma unroll
    for (int j = 0; j < 8; j++)
#pragma unroll
        for (int e = 0; e < 4; e++) o[j][e] = 0.f;
    float m0 = -INFINITY, m1 = -INFINITY, l0 = 0.f, l1 = 0.f;

    const int NT = Sv / 64;
    for (int t = 0; t < NT; t++) {
        if (t + 1 < NT) { CP_ASYNC_WAIT(1); } else { CP_ASYNC_WAIT(0); }
        // fallback per-tile dep wait (only when deps weren't all ready at start)
        if (t + 2 < NT && tid == 0 && !s_ready) {
            const int mbl = (t + 2) >> 1;
            while (atomicAdd(&g_qkvf[(b * 16 + mbl) * 24 + 8 + nbh], 0) == 0)
                __nanosleep(100);
            while (atomicAdd(&g_qkvf[(b * 16 + mbl) * 24 + 16 + nbh], 0) == 0)
                __nanosleep(100);
        }
        __syncthreads();
        if (t + 2 < NT) LOADKV((t + 2) % 3, t + 2);

        const uint32_t kvb = smb + AS_KV + (t % 3) * (2 * KVTB);
        const uint32_t KB = kvb, VB = kvb + KVTB;

        // ---- S = Q K^T (log2-scaled via Q) ----
        float s[8][4];
#pragma unroll
        for (int j = 0; j < 8; j++)
#pragma unroll
            for (int e = 0; e < 4; e++) s[j][e] = 0.f;

#pragma unroll
        for (int kt = 0; kt < 4; kt++) {
            uint32_t aQ[4];
            ldsm_x4(smb + AS_Q + aoffQ + kt * 32, aQ);
#pragma unroll
            for (int gn = 0; gn < 4; gn++) {
                uint32_t bb[4];
                ldsm_x4(KB + boffK + gn * (16 * SRA) + kt * 32, bb);
                mma_f16(s[2 * gn],     aQ, bb[0], bb[1]);
                mma_f16(s[2 * gn + 1], aQ, bb[2], bb[3]);
            }
        }

        // ---- online softmax (log2 domain) ----
        const uint32_t msb = smb + AS_MS + (uint32_t)((t * 64 + 2 * (lid & 3)) * 4);
        float tm0 = -INFINITY, tm1 = -INFINITY;
#pragma unroll
        for (int j = 0; j < 8; j++) {
            float mkx, mky;
            asm("ld.shared.v2.f32 {%0,%1}, [%2];" : "=f"(mkx), "=f"(mky) : "r"(msb + j * 32));
            s[j][0] += mkx;
            s[j][1] += mky;
            s[j][2] += mkx;
            s[j][3] += mky;
            tm0 = fmaxf(tm0, fmaxf(s[j][0], s[j][1]));
            tm1 = fmaxf(tm1, fmaxf(s[j][2], s[j][3]));
        }
        tm0 = fmaxf(tm0, __shfl_xor_sync(0xffffffffu, tm0, 1));
        tm0 = fmaxf(tm0, __shfl_xor_sync(0xffffffffu, tm0, 2));
        tm1 = fmaxf(tm1, __shfl_xor_sync(0xffffffffu, tm1, 1));
        tm1 = fmaxf(tm1, __shfl_xor_sync(0xffffffffu, tm1, 2));

        float al0 = 1.f, al1 = 1.f;
        const bool need = (tm0 > m0) || (tm1 > m1);
        if (__any_sync(0xffffffffu, need)) {
            const float mn0 = fmaxf(m0, tm0), mn1 = fmaxf(m1, tm1);
            al0 = exp2f(m0 - mn0);
            al1 = exp2f(m1 - mn1);
            m0 = mn0; m1 = mn1;
#pragma unroll
            for (int j = 0; j < 8; j++) {
                o[j][0] *= al0; o[j][1] *= al0;
                o[j][2] *= al1; o[j][3] *= al1;
            }
        }

        float rs0 = 0.f, rs1 = 0.f;
#pragma unroll
        for (int j = 0; j < 8; j++) {
            s[j][0] = exp2f(s[j][0] - m0);
            s[j][1] = exp2f(s[j][1] - m0);
            s[j][2] = exp2f(s[j][2] - m1);
            s[j][3] = exp2f(s[j][3] - m1);
            rs0 += s[j][0] + s[j][1];
            rs1 += s[j][2] + s[j][3];
        }
        rs0 += __shfl_xor_sync(0xffffffffu, rs0, 1);
        rs0 += __shfl_xor_sync(0xffffffffu, rs0, 2);
        rs1 += __shfl_xor_sync(0xffffffffu, rs1, 1);
        rs1 += __shfl_xor_sync(0xffffffffu, rs1, 2);
        l0 = l0 * al0 + rs0;
        l1 = l1 * al1 + rs1;

        // ---- O += P V ----
#pragma unroll
        for (int kt = 0; kt < 4; kt++) {
            uint32_t ap[4];
            ap[0] = pack_h2(s[2 * kt][0],     s[2 * kt][1]);
            ap[1] = pack_h2(s[2 * kt][2],     s[2 * kt][3]);
            ap[2] = pack_h2(s[2 * kt + 1][0], s[2 * kt + 1][1]);
            ap[3] = pack_h2(s[2 * kt + 1][2], s[2 * kt + 1][3]);
#pragma unroll
            for (int jp = 0; jp < 4; jp++) {
                uint32_t bb[4];
                ldsm_x4_t(VB + voffV + kt * (16 * SRA) + jp * 32, bb);
                mma_f16(o[2 * jp],     ap, bb[0], bb[1]);
                mma_f16(o[2 * jp + 1], ap, bb[2], bb[3]);
            }
        }
    }

    // ---- Epilogue: normalize, store fp16 av; signal row-block ----
    const float inv0 = 1.f / l0, inv1 = 1.f / l1;
    const int rg = q0 + wq_ * 16 + (lid >> 2);
    const size_t obase = (rowbase + rg) * Hv + hd0 + 2 * (lid & 3);
#pragma unroll
    for (int j = 0; j < 8; j++) {
        *(uint32_t*)(av + obase + j * 8)          = pack_h2(o[j][0] * inv0, o[j][1] * inv0);
        *(uint32_t*)(av + obase + 8 * Hv + j * 8) = pack_h2(o[j][2] * inv1, o[j][3] * inv1);
    }

    __threadfence();
    __syncthreads();
    if (tid == 0) atomicAdd(&g_flags[b * 16 + qblk], 1);
}

// ============================================================================
// Launch
// ============================================================================
extern "C" void kernel_launch(void* const* d_in, const int* in_sizes, int n_in,
                              void* d_out, int out_size)
{
    const float* x     = (const float*)d_in[0];
    const float* mask  = (const float*)d_in[1];
    const float* w_qkv = (const float*)d_in[2];
    const float* b_qkv = (const float*)d_in[3];
    const float* w_o   = (const float*)d_in[4];
    const float* b_o   = (const float*)d_in[5];
    float* out = (float*)d_out;

    cudaFuncSetAttribute(mega,
                         cudaFuncAttributeMaxDynamicSharedMemorySize, GSM_TOTAL);

    // 0) Front-end: x/wq -> fp16 (2x float4 per thread), mask scale, flag reset
    cvt_front_kernel<<<(NPAIRS + 255) / 256, 256>>>(x, w_qkv, mask);

    // 1) Mega: wo-cvt (64) + qkv (768, head-pair-interleaved) + attn (512) + proj (256)
    mega<<<1600, 256, GSM_TOTAL>>>(x, w_qkv, w_o, b_qkv, b_o, out);
}